// round 8
// baseline (speedup 1.0000x reference)
#include <cuda_runtime.h>
#include <cuda_bf16.h>
#include <math.h>
#include <stdint.h>

// Problem constants
#define DM   2048
#define NH   16
#define DH   128
#define SEQ  2048
#define BB   2
#define MROWS (BB*SEQ)     // 4096
#define BHN   (BB*NH)      // 32

// ---------------- scratch (static device arrays per harness rules) ----------
__device__ float g_q[BHN * SEQ * DH];
__device__ float g_k[BHN * SEQ * DH];
__device__ __nv_bfloat16 g_xh[MROWS * DM], g_xl[MROWS * DM];
__device__ __nv_bfloat16 g_wh[4 * DM * DM], g_wl[4 * DM * DM];   // q,k,v,o stacked
__device__ __nv_bfloat16 g_ah[MROWS * DM], g_al[MROWS * DM];     // att split
__device__ __nv_bfloat16 g_qh[BHN * SEQ * DH], g_ql[BHN * SEQ * DH];
__device__ __nv_bfloat16 g_kh[BHN * SEQ * DH], g_kl[BHN * SEQ * DH];
__device__ __nv_bfloat16 g_vh[BHN * SEQ * DH], g_vl[BHN * SEQ * DH];

// ---------------- helpers ---------------------------------------------------
__device__ __forceinline__ uint32_t smem_u32(const void* p) {
    uint32_t a;
    asm("{ .reg .u64 t; cvta.to.shared.u64 t, %1; cvt.u32.u64 %0, t; }"
        : "=r"(a) : "l"(p));
    return a;
}
__device__ __forceinline__ void cpa16(uint32_t s, const void* g) {
    asm volatile("cp.async.cg.shared.global [%0], [%1], 16;" :: "r"(s), "l"(g));
}
__device__ __forceinline__ void cpa_commit() {
    asm volatile("cp.async.commit_group;" ::: "memory");
}
template<int N>
__device__ __forceinline__ void cpa_wait() {
    asm volatile("cp.async.wait_group %0;" :: "n"(N) : "memory");
}
__device__ __forceinline__ void ldsm4(uint32_t* r, uint32_t addr) {
    asm volatile("ldmatrix.sync.aligned.m8n8.x4.shared.b16 {%0,%1,%2,%3}, [%4];"
                 : "=r"(r[0]), "=r"(r[1]), "=r"(r[2]), "=r"(r[3]) : "r"(addr));
}
__device__ __forceinline__ void ldsm4t(uint32_t* r, uint32_t addr) {
    asm volatile("ldmatrix.sync.aligned.m8n8.x4.trans.shared.b16 {%0,%1,%2,%3}, [%4];"
                 : "=r"(r[0]), "=r"(r[1]), "=r"(r[2]), "=r"(r[3]) : "r"(addr));
}
__device__ __forceinline__ void mma16816(float* c, const uint32_t* a, const uint32_t* b) {
    asm volatile("mma.sync.aligned.m16n8k16.row.col.f32.bf16.bf16.f32 "
                 "{%0,%1,%2,%3}, {%4,%5,%6,%7}, {%8,%9}, {%0,%1,%2,%3};"
                 : "+f"(c[0]), "+f"(c[1]), "+f"(c[2]), "+f"(c[3])
                 : "r"(a[0]), "r"(a[1]), "r"(a[2]), "r"(a[3]),
                   "r"(b[0]), "r"(b[1]));
}
__device__ __forceinline__ uint32_t pack_hi_trunc(float a, float b) {
    return __byte_perm(__float_as_uint(a), __float_as_uint(b), 0x7632);
}
__device__ __forceinline__ uint32_t pack_lo_res(float a, float b) {
    float ra = a - __uint_as_float(__float_as_uint(a) & 0xFFFF0000u);
    float rb = b - __uint_as_float(__float_as_uint(b) & 0xFFFF0000u);
    uint32_t r;
    asm("cvt.rn.bf16x2.f32 %0, %1, %2;" : "=r"(r) : "f"(rb), "f"(ra));
    return r;
}
__device__ __forceinline__ void tsplit(float x, __nv_bfloat16* h, __nv_bfloat16* l) {
    uint32_t hb = __float_as_uint(x) & 0xFFFF0000u;
    __nv_bfloat16_raw raw; raw.x = (unsigned short)(hb >> 16);
    *h = __nv_bfloat16(raw);
    *l = __float2bfloat16(x - __uint_as_float(hb));
}

// ---------------------------------------------------------------------------
// fp32 -> (hi, lo) bf16 split, vectorized x4 (single tensor)
// ---------------------------------------------------------------------------
__global__ void split_kernel(const float* __restrict__ src,
                             __nv_bfloat16* __restrict__ hi,
                             __nv_bfloat16* __restrict__ lo, int n4)
{
    int i = blockIdx.x * blockDim.x + threadIdx.x;
    if (i >= n4) return;
    float4 v = ((const float4*)src)[i];
    __nv_bfloat16 h0 = __float2bfloat16(v.x), h1 = __float2bfloat16(v.y);
    __nv_bfloat16 h2 = __float2bfloat16(v.z), h3 = __float2bfloat16(v.w);
    __nv_bfloat16 l0 = __float2bfloat16(v.x - __bfloat162float(h0));
    __nv_bfloat16 l1 = __float2bfloat16(v.y - __bfloat162float(h1));
    __nv_bfloat16 l2 = __float2bfloat16(v.z - __bfloat162float(h2));
    __nv_bfloat16 l3 = __float2bfloat16(v.w - __bfloat162float(h3));
    ((__nv_bfloat162*)hi)[2 * i]     = __halves2bfloat162(h0, h1);
    ((__nv_bfloat162*)hi)[2 * i + 1] = __halves2bfloat162(h2, h3);
    ((__nv_bfloat162*)lo)[2 * i]     = __halves2bfloat162(l0, l1);
    ((__nv_bfloat162*)lo)[2 * i + 1] = __halves2bfloat162(l2, l3);
}

// 4 weight matrices in one launch (blockIdx.y selects source)
struct Ptr4 { const float* p0; const float* p1; const float* p2; const float* p3; };
__global__ void split4_kernel(Ptr4 srcs,
                              __nv_bfloat16* __restrict__ hi,
                              __nv_bfloat16* __restrict__ lo, int n4per)
{
    int i = blockIdx.x * blockDim.x + threadIdx.x;
    if (i >= n4per) return;
    const float* src = (blockIdx.y == 0) ? srcs.p0 : (blockIdx.y == 1) ? srcs.p1
                     : (blockIdx.y == 2) ? srcs.p2 : srcs.p3;
    const size_t o = (size_t)blockIdx.y * n4per + i;
    float4 v = ((const float4*)src)[i];
    __nv_bfloat16 h0 = __float2bfloat16(v.x), h1 = __float2bfloat16(v.y);
    __nv_bfloat16 h2 = __float2bfloat16(v.z), h3 = __float2bfloat16(v.w);
    __nv_bfloat16 l0 = __float2bfloat16(v.x - __bfloat162float(h0));
    __nv_bfloat16 l1 = __float2bfloat16(v.y - __bfloat162float(h1));
    __nv_bfloat16 l2 = __float2bfloat16(v.z - __bfloat162float(h2));
    __nv_bfloat16 l3 = __float2bfloat16(v.w - __bfloat162float(h3));
    ((__nv_bfloat162*)hi)[2 * o]     = __halves2bfloat162(h0, h1);
    ((__nv_bfloat162*)hi)[2 * o + 1] = __halves2bfloat162(h2, h3);
    ((__nv_bfloat162*)lo)[2 * o]     = __halves2bfloat162(l0, l1);
    ((__nv_bfloat162*)lo)[2 * o + 1] = __halves2bfloat162(l2, l3);
}

// ---------------------------------------------------------------------------
// Shared GEMM machinery: 128x128 CTA tile, BK=32, 3-stage cp.async pipeline.
// ---------------------------------------------------------------------------
#define BK    32
#define TSTR  40
#define TILE_B (128 * TSTR * 2)     // 10240 B
#define BUF_B  (4 * TILE_B)         // 40960 B / stage
#define GM_SMEM (3 * BUF_B)         // 122880 B

// Per-stage tile load (Ah, Al, Wh, Wl), 128 rows x 32 bf16 each
__device__ __forceinline__ void gemm_issue(
    uint32_t sbase, int buf, int kt, int tid, int row0, int wrow0,
    const __nv_bfloat16* Ah, const __nv_bfloat16* Al,
    const __nv_bfloat16* Wh, const __nv_bfloat16* Wl)
{
    const __nv_bfloat16* gsrc[4] = {Ah, Al, Wh, Wl};
#pragma unroll
    for (int t = 0; t < 4; t++) {
        const __nv_bfloat16* g = gsrc[t];
        const int rb = (t < 2) ? row0 : wrow0;
        const uint32_t sb = sbase + buf * BUF_B + t * TILE_B;
#pragma unroll
        for (int i = 0; i < 2; i++) {
            const int ch = tid + i * 256;
            const int r = ch >> 2, c = ch & 3;
            cpa16(sb + r * (TSTR * 2) + c * 16,
                  g + (size_t)(rb + r) * DM + kt * BK + c * 8);
        }
    }
    cpa_commit();
}

// Mainloop body: accumulate one K-slab from stage buffer sb
__device__ __forceinline__ void gemm_slab(
    uint32_t sb, int wm, int wn, int a_r, int a_kb, int b_nt, int b_kb, int l7,
    float acc[4][4][4])
{
#pragma unroll
    for (int kh = 0; kh < 2; kh++) {
        uint32_t afh[4][4], afl[4][4];
#pragma unroll
        for (int mt = 0; mt < 4; mt++) {
            const uint32_t ad = sb +
                (wm + mt * 16 + a_r) * (TSTR * 2) + (kh * 16 + a_kb) * 2;
            ldsm4(afh[mt], ad);
            ldsm4(afl[mt], ad + TILE_B);
        }
        uint32_t bfh[8], bfl[8];
#pragma unroll
        for (int g = 0; g < 2; g++) {
            const uint32_t bd = sb + 2 * TILE_B +
                (wn + (2 * g + b_nt) * 8 + l7) * (TSTR * 2) +
                (kh * 16 + b_kb) * 2;
            ldsm4(&bfh[g * 4], bd);
            ldsm4(&bfl[g * 4], bd + TILE_B);
        }
#pragma unroll
        for (int mt = 0; mt < 4; mt++)
#pragma unroll
            for (int nt = 0; nt < 4; nt++) {
                float* c = acc[mt][nt];
                mma16816(c, afh[mt], &bfh[nt * 2]);
                mma16816(c, afh[mt], &bfl[nt * 2]);
                mma16816(c, afl[mt], &bfh[nt * 2]);
            }
    }
}

// ---------------------------------------------------------------------------
// Fused QKV projection GEMM. Grid (6144/128 = 48, MROWS/128 = 32).
// W hi/lo stacked [6144 x 2048]. Q,K emit fp32 (B,H,T,Dh) for RoPE;
// V emits truncation-split bf16 hi/lo directly (no RoPE needed).
// ---------------------------------------------------------------------------
__global__ void __launch_bounds__(256) gemm_qkv(
    const __nv_bfloat16* __restrict__ Ah, const __nv_bfloat16* __restrict__ Al,
    const __nv_bfloat16* __restrict__ Wh, const __nv_bfloat16* __restrict__ Wl,
    const float* __restrict__ bq, const float* __restrict__ bk,
    const float* __restrict__ bv,
    float* __restrict__ q, float* __restrict__ k,
    __nv_bfloat16* __restrict__ vh, __nv_bfloat16* __restrict__ vl)
{
    extern __shared__ __align__(128) char smem[];
    const uint32_t sbase = smem_u32(smem);
    const int tid  = threadIdx.x;
    const int wid  = tid >> 5;
    const int lane = tid & 31;
    const int row0  = blockIdx.y * 128;
    const int col0g = blockIdx.x * 128;           // 0..6143 (stacked W rows)
    const int proj  = col0g >> 11;
    const float* bias = (proj == 0) ? bq : (proj == 1) ? bk : bv;
    const int wm = (wid >> 2) * 64;
    const int wn = (wid & 3) * 32;

    float acc[4][4][4];
#pragma unroll
    for (int i = 0; i < 4; i++)
#pragma unroll
        for (int j = 0; j < 4; j++)
#pragma unroll
            for (int c = 0; c < 4; c++) acc[i][j][c] = 0.f;

    const int mi = lane >> 3;
    const int l7 = lane & 7;
    const int a_r  = ((mi & 1) << 3) + l7;
    const int a_kb = (mi >> 1) << 3;
    const int b_nt = mi >> 1;
    const int b_kb = (mi & 1) << 3;

    const int NKT = DM / BK;
    gemm_issue(sbase, 0, 0, tid, row0, col0g, Ah, Al, Wh, Wl);
    gemm_issue(sbase, 1, 1, tid, row0, col0g, Ah, Al, Wh, Wl);

    for (int kt = 0; kt < NKT; kt++) {
        if (kt + 1 < NKT) cpa_wait<1>(); else cpa_wait<0>();
        __syncthreads();
        if (kt + 2 < NKT)
            gemm_issue(sbase, (kt + 2) % 3, kt + 2, tid, row0, col0g, Ah, Al, Wh, Wl);
        gemm_slab(sbase + (kt % 3) * BUF_B, wm, wn, a_r, a_kb, b_nt, b_kb, l7, acc);
    }

    // epilogue: scatter to (B,H,T,Dh); V goes straight to split-bf16
#pragma unroll
    for (int mt = 0; mt < 4; mt++) {
#pragma unroll
        for (int nt = 0; nt < 4; nt++) {
            const int nn = (col0g + wn + nt * 8 + (lane & 3) * 2) & (DM - 1);
            const float b0 = bias[nn], b1 = bias[nn + 1];
            const int h  = nn >> 7;
            const int d0 = nn & (DH - 1);
#pragma unroll
            for (int half = 0; half < 2; half++) {
                const int rr = row0 + wm + mt * 16 + (lane >> 2) + half * 8;
                const int b  = rr >> 11;
                const int tt = rr & (SEQ - 1);
                const float o0 = acc[mt][nt][half * 2 + 0] + b0;
                const float o1 = acc[mt][nt][half * 2 + 1] + b1;
                const size_t off = (((size_t)(b * NH + h)) * SEQ + tt) * DH + d0;
                if (proj == 0) {
                    *(float2*)(q + off) = make_float2(o0, o1);
                } else if (proj == 1) {
                    *(float2*)(k + off) = make_float2(o0, o1);
                } else {
                    *(uint32_t*)(vh + off) = pack_hi_trunc(o0, o1);
                    *(uint32_t*)(vl + off) = pack_lo_res(o0, o1);
                }
            }
        }
    }
}

// ---------------------------------------------------------------------------
// Output projection GEMM (plain row-major out). Grid (16, 32).
// ---------------------------------------------------------------------------
__global__ void __launch_bounds__(256) gemm_out(
    const __nv_bfloat16* __restrict__ Ah, const __nv_bfloat16* __restrict__ Al,
    const __nv_bfloat16* __restrict__ Wh, const __nv_bfloat16* __restrict__ Wl,
    const float* __restrict__ bias, float* __restrict__ C)
{
    extern __shared__ __align__(128) char smem[];
    const uint32_t sbase = smem_u32(smem);
    const int tid  = threadIdx.x;
    const int wid  = tid >> 5;
    const int lane = tid & 31;
    const int row0 = blockIdx.y * 128;
    const int col0 = blockIdx.x * 128;
    const int wm = (wid >> 2) * 64;
    const int wn = (wid & 3) * 32;

    float acc[4][4][4];
#pragma unroll
    for (int i = 0; i < 4; i++)
#pragma unroll
        for (int j = 0; j < 4; j++)
#pragma unroll
            for (int c = 0; c < 4; c++) acc[i][j][c] = 0.f;

    const int mi = lane >> 3;
    const int l7 = lane & 7;
    const int a_r  = ((mi & 1) << 3) + l7;
    const int a_kb = (mi >> 1) << 3;
    const int b_nt = mi >> 1;
    const int b_kb = (mi & 1) << 3;

    const int NKT = DM / BK;
    gemm_issue(sbase, 0, 0, tid, row0, col0, Ah, Al, Wh, Wl);
    gemm_issue(sbase, 1, 1, tid, row0, col0, Ah, Al, Wh, Wl);

    for (int kt = 0; kt < NKT; kt++) {
        if (kt + 1 < NKT) cpa_wait<1>(); else cpa_wait<0>();
        __syncthreads();
        if (kt + 2 < NKT)
            gemm_issue(sbase, (kt + 2) % 3, kt + 2, tid, row0, col0, Ah, Al, Wh, Wl);
        gemm_slab(sbase + (kt % 3) * BUF_B, wm, wn, a_r, a_kb, b_nt, b_kb, l7, acc);
    }

#pragma unroll
    for (int mt = 0; mt < 4; mt++) {
#pragma unroll
        for (int nt = 0; nt < 4; nt++) {
            const int cc = col0 + wn + nt * 8 + (lane & 3) * 2;
            const float b0 = bias[cc], b1 = bias[cc + 1];
#pragma unroll
            for (int half = 0; half < 2; half++) {
                const int rr = row0 + wm + mt * 16 + (lane >> 2) + half * 8;
                float2 o;
                o.x = acc[mt][nt][half * 2 + 0] + b0;
                o.y = acc[mt][nt][half * 2 + 1] + b1;
                *(float2*)(C + (size_t)rr * DM + cc) = o;
            }
        }
    }
}

// ---------------------------------------------------------------------------
// RoPE + scale + truncation-split of q,k -> bf16 hi/lo arrays (V done in GEMM)
// ---------------------------------------------------------------------------
__global__ void rope_split(const float* __restrict__ q, const float* __restrict__ k,
                           const float* __restrict__ sn, const float* __restrict__ cs,
                           __nv_bfloat16* __restrict__ qh, __nv_bfloat16* __restrict__ ql,
                           __nv_bfloat16* __restrict__ kh, __nv_bfloat16* __restrict__ kl)
{
    const int idx = blockIdx.x * blockDim.x + threadIdx.x;   // BHN*SEQ*64
    const int d  = idx & 63;
    const int t  = (idx >> 6) & (SEQ - 1);
    const int bh = idx >> 17;
    const float s = sn[t * 64 + d];
    const float c = cs[t * 64 + d];
    const size_t base = ((size_t)bh * SEQ + t) * DH;
    const float scale = 0.08838834764831845f;   // 1/sqrt(128)

    float q1 = q[base + d], q2 = q[base + 64 + d];
    float rq1 = (q1 * c - q2 * s) * scale;
    float rq2 = (q1 * s + q2 * c) * scale;
    __nv_bfloat16 hh, ll;
    tsplit(rq1, &hh, &ll); qh[base + d] = hh;      ql[base + d] = ll;
    tsplit(rq2, &hh, &ll); qh[base + 64 + d] = hh; ql[base + 64 + d] = ll;

    float k1 = k[base + d], k2 = k[base + 64 + d];
    float rk1 = k1 * c - k2 * s;
    float rk2 = k1 * s + k2 * c;
    tsplit(rk1, &hh, &ll); kh[base + d] = hh;      kl[base + d] = ll;
    tsplit(rk2, &hh, &ll); kh[base + 64 + d] = hh; kl[base + 64 + d] = ll;
}

// ---------------------------------------------------------------------------
// Tensor-core causal flash attention, split-bf16, single sync per kv-tile.
// ---------------------------------------------------------------------------
#define FSTR   272
#define QT_B   (128 * FSTR)
#define KT_B   (64 * FSTR)
#define FBUF   (4 * KT_B)
#define FL_SMEM (2 * QT_B + 2 * FBUF)  // 208896

__global__ void __launch_bounds__(256) flash_mma(
    const __nv_bfloat16* __restrict__ qh, const __nv_bfloat16* __restrict__ ql,
    const __nv_bfloat16* __restrict__ kh, const __nv_bfloat16* __restrict__ kl,
    const __nv_bfloat16* __restrict__ vh, const __nv_bfloat16* __restrict__ vl,
    __nv_bfloat16* __restrict__ att_hi, __nv_bfloat16* __restrict__ att_lo)
{
    extern __shared__ __align__(128) char smem[];
    const uint32_t sbase = smem_u32(smem);
    const int tid  = threadIdx.x;
    const int wid  = tid >> 5;
    const int lane = tid & 31;
    const int qt = (int)gridDim.x - 1 - (int)blockIdx.x;  // heavy tiles first
    const int bhid = blockIdx.y;
    const size_t hb = (size_t)bhid * SEQ * DH;

    const int mi_ = lane >> 3;
    const int l7  = lane & 7;
    const int a_r  = ((mi_ & 1) << 3) + l7;
    const int a_kb = (mi_ >> 1) << 3;
    const int b_nt = mi_ >> 1;
    const int b_kb = (mi_ & 1) << 3;

    // ---- load Q tile (hi+lo), its own commit group ----
    {
        const __nv_bfloat16* src[2] = {qh, ql};
#pragma unroll
        for (int i = 0; i < 16; i++) {
            const int idx = tid + i * 256;
            const int t = idx >> 11, r = (idx >> 4) & 127, c = idx & 15;
            cpa16(sbase + t * QT_B + r * FSTR + c * 16,
                  src[t] + hb + (size_t)(qt * 128 + r) * DH + c * 8);
        }
        cpa_commit();
    }

    const __nv_bfloat16* kvsrc[4] = {kh, kl, vh, vl};
    auto issue_kv = [&](int j, int buf) {
        const uint32_t base = sbase + 2 * QT_B + buf * FBUF;
#pragma unroll
        for (int i = 0; i < 16; i++) {
            const int idx = tid + i * 256;
            const int s = idx >> 10, r = (idx >> 4) & 63, c = idx & 15;
            cpa16(base + s * KT_B + r * FSTR + c * 16,
                  kvsrc[s] + hb + (size_t)(j * 64 + r) * DH + c * 8);
        }
        cpa_commit();
    };

    float O[16][4];
#pragma unroll
    for (int nt = 0; nt < 16; nt++)
#pragma unroll
        for (int c = 0; c < 4; c++) O[nt][c] = 0.f;
    float mi0 = -INFINITY, mi1 = -INFINITY, li0 = 0.f, li1 = 0.f;

    const int rbase = qt * 128 + wid * 16;
    const int jmax = 2 * qt + 1;
    issue_kv(0, 0);

    for (int j = 0; j <= jmax; j++) {
        cpa_wait<0>();
        __syncthreads();
        if (j < jmax) issue_kv(j + 1, (j + 1) & 1);
        const int buf = j & 1;

        const bool active = (j * 64 <= rbase + 15);
        if (active) {
            const uint32_t kb = sbase + 2 * QT_B + buf * FBUF;

            // ---- S = Q K^T (split 3-term) ----
            float S[8][4];
#pragma unroll
            for (int nf = 0; nf < 8; nf++)
#pragma unroll
                for (int c = 0; c < 4; c++) S[nf][c] = 0.f;

#pragma unroll
            for (int k16 = 0; k16 < 8; k16++) {
                uint32_t aqh[4], aql[4];
                const uint32_t qa = sbase + (wid * 16 + a_r) * FSTR +
                                    (k16 * 16 + a_kb) * 2;
                ldsm4(aqh, qa);
                ldsm4(aql, qa + QT_B);
                uint32_t kfh[16], kfl[16];
#pragma unroll
                for (int g = 0; g < 4; g++) {
                    const uint32_t ka = kb + ((2 * g + b_nt) * 8 + l7) * FSTR +
                                        (k16 * 16 + b_kb) * 2;
                    ldsm4(&kfh[g * 4], ka);
                    ldsm4(&kfl[g * 4], ka + KT_B);
                }
#pragma unroll
                for (int nf = 0; nf < 8; nf++) {
                    const uint32_t* Bh = &kfh[nf * 2];
                    const uint32_t* Bl = &kfl[nf * 2];
                    mma16816(S[nf], aqh, Bh);
                    mma16816(S[nf], aqh, Bl);
                    mma16816(S[nf], aql, Bh);
                }
            }

            // ---- causal mask ----
            if (j * 64 + 63 > rbase) {
                const int r0 = rbase + (lane >> 2), r1 = r0 + 8;
#pragma unroll
                for (int nf = 0; nf < 8; nf++) {
                    const int c0 = j * 64 + nf * 8 + (lane & 3) * 2;
                    if (c0 > r0)     S[nf][0] = -1e30f;
                    if (c0 + 1 > r0) S[nf][1] = -1e30f;
                    if (c0 > r1)     S[nf][2] = -1e30f;
                    if (c0 + 1 > r1) S[nf][3] = -1e30f;
                }
            }

            // ---- online softmax ----
            float rx0 = -1e30f, rx1 = -1e30f;
#pragma unroll
            for (int nf = 0; nf < 8; nf++) {
                rx0 = fmaxf(rx0, fmaxf(S[nf][0], S[nf][1]));
                rx1 = fmaxf(rx1, fmaxf(S[nf][2], S[nf][3]));
            }
            rx0 = fmaxf(rx0, __shfl_xor_sync(0xffffffffu, rx0, 1));
            rx0 = fmaxf(rx0, __shfl_xor_sync(0xffffffffu, rx0, 2));
            rx1 = fmaxf(rx1, __shfl_xor_sync(0xffffffffu, rx1, 1));
            rx1 = fmaxf(rx1, __shfl_xor_sync(0xffffffffu, rx1, 2));
            const float mn0 = fmaxf(mi0, rx0), mn1 = fmaxf(mi1, rx1);
            const float al0 = __expf(mi0 - mn0), al1 = __expf(mi1 - mn1);
            float s0 = 0.f, s1 = 0.f;
#pragma unroll
            for (int nf = 0; nf < 8; nf++) {
                S[nf][0] = __expf(S[nf][0] - mn0);
                S[nf][1] = __expf(S[nf][1] - mn0);
                S[nf][2] = __expf(S[nf][2] - mn1);
                S[nf][3] = __expf(S[nf][3] - mn1);
                s0 += S[nf][0] + S[nf][1];
                s1 += S[nf][2] + S[nf][3];
            }
            s0 += __shfl_xor_sync(0xffffffffu, s0, 1);
            s0 += __shfl_xor_sync(0xffffffffu, s0, 2);
            s1 += __shfl_xor_sync(0xffffffffu, s1, 1);
            s1 += __shfl_xor_sync(0xffffffffu, s1, 2);
            li0 = li0 * al0 + s0; mi0 = mn0;
            li1 = li1 * al1 + s1; mi1 = mn1;
#pragma unroll
            for (int nt = 0; nt < 16; nt++) {
                O[nt][0] *= al0; O[nt][1] *= al0;
                O[nt][2] *= al1; O[nt][3] *= al1;
            }

            // ---- pack P to A-fragments (truncation split) ----
            uint32_t Ph[4][4], Pl[4][4];
#pragma unroll
            for (int kc = 0; kc < 4; kc++) {
                Ph[kc][0] = pack_hi_trunc(S[2*kc][0],   S[2*kc][1]);
                Ph[kc][1] = pack_hi_trunc(S[2*kc][2],   S[2*kc][3]);
                Ph[kc][2] = pack_hi_trunc(S[2*kc+1][0], S[2*kc+1][1]);
                Ph[kc][3] = pack_hi_trunc(S[2*kc+1][2], S[2*kc+1][3]);
                Pl[kc][0] = pack_lo_res(S[2*kc][0],   S[2*kc][1]);
                Pl[kc][1] = pack_lo_res(S[2*kc][2],   S[2*kc][3]);
                Pl[kc][2] = pack_lo_res(S[2*kc+1][0], S[2*kc+1][1]);
                Pl[kc][3] = pack_lo_res(S[2*kc+1][2], S[2*kc+1][3]);
            }

            // ---- O += P V (split 3-term) ----
            const uint32_t vb = kb + 2 * KT_B;
#pragma unroll
            for (int kc = 0; kc < 4; kc++) {
#pragma unroll
                for (int half = 0; half < 2; half++) {
                    uint32_t vfh[16], vfl[16];
#pragma unroll
                    for (int g = 0; g < 4; g++) {
                        const int gg = half * 4 + g;
                        const uint32_t va = vb +
                            (kc * 16 + ((mi_ & 1) << 3) + l7) * FSTR +
                            (gg * 16 + ((mi_ >> 1) << 3)) * 2;
                        ldsm4t(&vfh[g * 4], va);
                        ldsm4t(&vfl[g * 4], va + KT_B);
                    }
#pragma unroll
                    for (int nf = 0; nf < 8; nf++) {
                        const int nt = half * 8 + nf;
                        const uint32_t* Bh = &vfh[nf * 2];
                        const uint32_t* Bl = &vfl[nf * 2];
                        mma16816(O[nt], Ph[kc], Bh);
                        mma16816(O[nt], Ph[kc], Bl);
                        mma16816(O[nt], Pl[kc], Bh);
                    }
                }
            }
        }
    }

    // ---- epilogue ----
    const float inv0 = 1.f / li0, inv1 = 1.f / li1;
    const int b = bhid >> 4, h = bhid & 15;
    const int t0 = rbase + (lane >> 2), t1 = t0 + 8;
#pragma unroll
    for (int nt = 0; nt < 16; nt++) {
        const int col = h * DH + nt * 8 + (lane & 3) * 2;
        const size_t o0 = ((size_t)(b * SEQ) + t0) * DM + col;
        const size_t o1 = ((size_t)(b * SEQ) + t1) * DM + col;
        const float x0 = O[nt][0] * inv0, x1 = O[nt][1] * inv0;
        const float y0 = O[nt][2] * inv1, y1 = O[nt][3] * inv1;
        *(uint32_t*)(att_hi + o0) = pack_hi_trunc(x0, x1);
        *(uint32_t*)(att_lo + o0) = pack_lo_res(x0, x1);
        *(uint32_t*)(att_hi + o1) = pack_hi_trunc(y0, y1);
        *(uint32_t*)(att_lo + o1) = pack_lo_res(y0, y1);
    }
}

// ---------------------------------------------------------------------------
extern "C" void kernel_launch(void* const* d_in, const int* in_sizes, int n_in,
                              void* d_out, int out_size)
{
    (void)in_sizes; (void)n_in; (void)out_size;
    const float* x  = (const float*)d_in[0];
    const float* Wq = (const float*)d_in[1];
    const float* bq = (const float*)d_in[2];
    const float* Wk = (const float*)d_in[3];
    const float* bk = (const float*)d_in[4];
    const float* Wv = (const float*)d_in[5];
    const float* bv = (const float*)d_in[6];
    const float* Wo = (const float*)d_in[7];
    const float* bo = (const float*)d_in[8];
    const float* sn = (const float*)d_in[9];
    const float* cs = (const float*)d_in[10];
    float* out = (float*)d_out;

    float *q, *k;
    __nv_bfloat16 *xh, *xl, *wh, *wl, *ah, *al;
    __nv_bfloat16 *qh, *ql, *kh, *kl, *vh, *vl;
    cudaGetSymbolAddress((void**)&q,  g_q);
    cudaGetSymbolAddress((void**)&k,  g_k);
    cudaGetSymbolAddress((void**)&xh, g_xh);
    cudaGetSymbolAddress((void**)&xl, g_xl);
    cudaGetSymbolAddress((void**)&wh, g_wh);
    cudaGetSymbolAddress((void**)&wl, g_wl);
    cudaGetSymbolAddress((void**)&ah, g_ah);
    cudaGetSymbolAddress((void**)&al, g_al);
    cudaGetSymbolAddress((void**)&qh, g_qh);
    cudaGetSymbolAddress((void**)&ql, g_ql);
    cudaGetSymbolAddress((void**)&kh, g_kh);
    cudaGetSymbolAddress((void**)&kl, g_kl);
    cudaGetSymbolAddress((void**)&vh, g_vh);
    cudaGetSymbolAddress((void**)&vl, g_vl);

    cudaFuncSetAttribute(gemm_qkv, cudaFuncAttributeMaxDynamicSharedMemorySize, GM_SMEM);
    cudaFuncSetAttribute(gemm_out, cudaFuncAttributeMaxDynamicSharedMemorySize, GM_SMEM);
    cudaFuncSetAttribute(flash_mma, cudaFuncAttributeMaxDynamicSharedMemorySize, FL_SMEM);

    // split conversions: x, then all 4 weight matrices in one launch
    split_kernel<<<(MROWS * DM / 4) / 256, 256>>>(x, xh, xl, MROWS * DM / 4);
    const int wn4 = DM * DM / 4;
    Ptr4 wsrc = {Wq, Wk, Wv, Wo};
    split4_kernel<<<dim3(wn4 / 256, 4), 256>>>(wsrc, wh, wl, wn4);

    // Fused QKV projection (48 x 32 = 1536 CTAs); V split emitted directly
    gemm_qkv<<<dim3(3 * DM / 128, MROWS / 128), 256, GM_SMEM>>>(
        xh, xl, wh, wl, bq, bk, bv, q, k, vh, vl);

    // RoPE + scale + split to bf16 hi/lo (q, k only)
    rope_split<<<(BHN * SEQ * 64) / 256, 256>>>(q, k, sn, cs, qh, ql, kh, kl);

    // Tensor-core flash attention (emits split-bf16 att)
    flash_mma<<<dim3(SEQ / 128, BHN), 256, FL_SMEM>>>(qh, ql, kh, kl, vh, vl, ah, al);

    // Output projection
    gemm_out<<<dim3(DM / 128, MROWS / 128), 256, GM_SMEM>>>(
        ah, al, wh + 3 * (size_t)DM * DM, wl + 3 * (size_t)DM * DM, bo, out);
}

// round 9
// speedup vs baseline: 1.1444x; 1.1444x over previous
#include <cuda_runtime.h>
#include <cuda_bf16.h>
#include <math.h>
#include <stdint.h>

// Problem constants
#define DM   2048
#define NH   16
#define DH   128
#define SEQ  2048
#define BB   2
#define MROWS (BB*SEQ)     // 4096
#define BHN   (BB*NH)      // 32

// ---------------- scratch (static device arrays per harness rules) ----------
__device__ float g_q[BHN * SEQ * DH];
__device__ float g_k[BHN * SEQ * DH];
__device__ __nv_bfloat16 g_xh[MROWS * DM], g_xl[MROWS * DM];
__device__ __nv_bfloat16 g_wh[4 * DM * DM], g_wl[4 * DM * DM];   // q,k,v,o stacked
__device__ __nv_bfloat16 g_ah[MROWS * DM], g_al[MROWS * DM];     // att split
__device__ __nv_bfloat16 g_qh[BHN * SEQ * DH], g_ql[BHN * SEQ * DH];
__device__ __nv_bfloat16 g_kh[BHN * SEQ * DH], g_kl[BHN * SEQ * DH];
__device__ __nv_bfloat16 g_vh[BHN * SEQ * DH], g_vl[BHN * SEQ * DH];

// ---------------- helpers ---------------------------------------------------
__device__ __forceinline__ uint32_t smem_u32(const void* p) {
    uint32_t a;
    asm("{ .reg .u64 t; cvta.to.shared.u64 t, %1; cvt.u32.u64 %0, t; }"
        : "=r"(a) : "l"(p));
    return a;
}
__device__ __forceinline__ void cpa16(uint32_t s, const void* g) {
    asm volatile("cp.async.cg.shared.global [%0], [%1], 16;" :: "r"(s), "l"(g));
}
__device__ __forceinline__ void cpa_commit() {
    asm volatile("cp.async.commit_group;" ::: "memory");
}
template<int N>
__device__ __forceinline__ void cpa_wait() {
    asm volatile("cp.async.wait_group %0;" :: "n"(N) : "memory");
}
__device__ __forceinline__ void ldsm4(uint32_t* r, uint32_t addr) {
    asm volatile("ldmatrix.sync.aligned.m8n8.x4.shared.b16 {%0,%1,%2,%3}, [%4];"
                 : "=r"(r[0]), "=r"(r[1]), "=r"(r[2]), "=r"(r[3]) : "r"(addr));
}
__device__ __forceinline__ void ldsm4t(uint32_t* r, uint32_t addr) {
    asm volatile("ldmatrix.sync.aligned.m8n8.x4.trans.shared.b16 {%0,%1,%2,%3}, [%4];"
                 : "=r"(r[0]), "=r"(r[1]), "=r"(r[2]), "=r"(r[3]) : "r"(addr));
}
__device__ __forceinline__ void mma16816(float* c, const uint32_t* a, const uint32_t* b) {
    asm volatile("mma.sync.aligned.m16n8k16.row.col.f32.bf16.bf16.f32 "
                 "{%0,%1,%2,%3}, {%4,%5,%6,%7}, {%8,%9}, {%0,%1,%2,%3};"
                 : "+f"(c[0]), "+f"(c[1]), "+f"(c[2]), "+f"(c[3])
                 : "r"(a[0]), "r"(a[1]), "r"(a[2]), "r"(a[3]),
                   "r"(b[0]), "r"(b[1]));
}
__device__ __forceinline__ uint32_t pack_hi_trunc(float a, float b) {
    return __byte_perm(__float_as_uint(a), __float_as_uint(b), 0x7632);
}
__device__ __forceinline__ uint32_t pack_lo_res(float a, float b) {
    float ra = a - __uint_as_float(__float_as_uint(a) & 0xFFFF0000u);
    float rb = b - __uint_as_float(__float_as_uint(b) & 0xFFFF0000u);
    uint32_t r;
    asm("cvt.rn.bf16x2.f32 %0, %1, %2;" : "=r"(r) : "f"(rb), "f"(ra));
    return r;
}
__device__ __forceinline__ void tsplit(float x, __nv_bfloat16* h, __nv_bfloat16* l) {
    uint32_t hb = __float_as_uint(x) & 0xFFFF0000u;
    __nv_bfloat16_raw raw; raw.x = (unsigned short)(hb >> 16);
    *h = __nv_bfloat16(raw);
    *l = __float2bfloat16(x - __uint_as_float(hb));
}

// ---------------------------------------------------------------------------
// fp32 -> (hi, lo) bf16 split, vectorized x4 (single tensor)
// ---------------------------------------------------------------------------
__global__ void split_kernel(const float* __restrict__ src,
                             __nv_bfloat16* __restrict__ hi,
                             __nv_bfloat16* __restrict__ lo, int n4)
{
    int i = blockIdx.x * blockDim.x + threadIdx.x;
    if (i >= n4) return;
    float4 v = ((const float4*)src)[i];
    __nv_bfloat16 h0 = __float2bfloat16(v.x), h1 = __float2bfloat16(v.y);
    __nv_bfloat16 h2 = __float2bfloat16(v.z), h3 = __float2bfloat16(v.w);
    __nv_bfloat16 l0 = __float2bfloat16(v.x - __bfloat162float(h0));
    __nv_bfloat16 l1 = __float2bfloat16(v.y - __bfloat162float(h1));
    __nv_bfloat16 l2 = __float2bfloat16(v.z - __bfloat162float(h2));
    __nv_bfloat16 l3 = __float2bfloat16(v.w - __bfloat162float(h3));
    ((__nv_bfloat162*)hi)[2 * i]     = __halves2bfloat162(h0, h1);
    ((__nv_bfloat162*)hi)[2 * i + 1] = __halves2bfloat162(h2, h3);
    ((__nv_bfloat162*)lo)[2 * i]     = __halves2bfloat162(l0, l1);
    ((__nv_bfloat162*)lo)[2 * i + 1] = __halves2bfloat162(l2, l3);
}

// 4 weight matrices in one launch (blockIdx.y selects source)
struct Ptr4 { const float* p0; const float* p1; const float* p2; const float* p3; };
__global__ void split4_kernel(Ptr4 srcs,
                              __nv_bfloat16* __restrict__ hi,
                              __nv_bfloat16* __restrict__ lo, int n4per)
{
    int i = blockIdx.x * blockDim.x + threadIdx.x;
    if (i >= n4per) return;
    const float* src = (blockIdx.y == 0) ? srcs.p0 : (blockIdx.y == 1) ? srcs.p1
                     : (blockIdx.y == 2) ? srcs.p2 : srcs.p3;
    const size_t o = (size_t)blockIdx.y * n4per + i;
    float4 v = ((const float4*)src)[i];
    __nv_bfloat16 h0 = __float2bfloat16(v.x), h1 = __float2bfloat16(v.y);
    __nv_bfloat16 h2 = __float2bfloat16(v.z), h3 = __float2bfloat16(v.w);
    __nv_bfloat16 l0 = __float2bfloat16(v.x - __bfloat162float(h0));
    __nv_bfloat16 l1 = __float2bfloat16(v.y - __bfloat162float(h1));
    __nv_bfloat16 l2 = __float2bfloat16(v.z - __bfloat162float(h2));
    __nv_bfloat16 l3 = __float2bfloat16(v.w - __bfloat162float(h3));
    ((__nv_bfloat162*)hi)[2 * o]     = __halves2bfloat162(h0, h1);
    ((__nv_bfloat162*)hi)[2 * o + 1] = __halves2bfloat162(h2, h3);
    ((__nv_bfloat162*)lo)[2 * o]     = __halves2bfloat162(l0, l1);
    ((__nv_bfloat162*)lo)[2 * o + 1] = __halves2bfloat162(l2, l3);
}

// ---------------------------------------------------------------------------
// Shared GEMM machinery: 128x128 CTA tile, BK=32, 2-stage cp.async pipeline.
// 2 stages -> 81920 B smem -> 2 CTAs/SM (occupancy is what matters here;
// the 3-stage variant measured +114us from dropping to 1 CTA/SM).
// ---------------------------------------------------------------------------
#define BK    32
#define TSTR  40
#define TILE_B (128 * TSTR * 2)     // 10240 B
#define BUF_B  (4 * TILE_B)         // 40960 B / stage
#define GM_SMEM (2 * BUF_B)         // 81920 B

// Per-stage tile load (Ah, Al, Wh, Wl), 128 rows x 32 bf16 each
__device__ __forceinline__ void gemm_issue(
    uint32_t sbase, int buf, int kt, int tid, int row0, int wrow0,
    const __nv_bfloat16* Ah, const __nv_bfloat16* Al,
    const __nv_bfloat16* Wh, const __nv_bfloat16* Wl)
{
    const __nv_bfloat16* gsrc[4] = {Ah, Al, Wh, Wl};
#pragma unroll
    for (int t = 0; t < 4; t++) {
        const __nv_bfloat16* g = gsrc[t];
        const int rb = (t < 2) ? row0 : wrow0;
        const uint32_t sb = sbase + buf * BUF_B + t * TILE_B;
#pragma unroll
        for (int i = 0; i < 2; i++) {
            const int ch = tid + i * 256;
            const int r = ch >> 2, c = ch & 3;
            cpa16(sb + r * (TSTR * 2) + c * 16,
                  g + (size_t)(rb + r) * DM + kt * BK + c * 8);
        }
    }
    cpa_commit();
}

// Mainloop body: accumulate one K-slab from stage buffer sb
__device__ __forceinline__ void gemm_slab(
    uint32_t sb, int wm, int wn, int a_r, int a_kb, int b_nt, int b_kb, int l7,
    float acc[4][4][4])
{
#pragma unroll
    for (int kh = 0; kh < 2; kh++) {
        uint32_t afh[4][4], afl[4][4];
#pragma unroll
        for (int mt = 0; mt < 4; mt++) {
            const uint32_t ad = sb +
                (wm + mt * 16 + a_r) * (TSTR * 2) + (kh * 16 + a_kb) * 2;
            ldsm4(afh[mt], ad);
            ldsm4(afl[mt], ad + TILE_B);
        }
        uint32_t bfh[8], bfl[8];
#pragma unroll
        for (int g = 0; g < 2; g++) {
            const uint32_t bd = sb + 2 * TILE_B +
                (wn + (2 * g + b_nt) * 8 + l7) * (TSTR * 2) +
                (kh * 16 + b_kb) * 2;
            ldsm4(&bfh[g * 4], bd);
            ldsm4(&bfl[g * 4], bd + TILE_B);
        }
#pragma unroll
        for (int mt = 0; mt < 4; mt++)
#pragma unroll
            for (int nt = 0; nt < 4; nt++) {
                float* c = acc[mt][nt];
                mma16816(c, afh[mt], &bfh[nt * 2]);
                mma16816(c, afh[mt], &bfl[nt * 2]);
                mma16816(c, afl[mt], &bfh[nt * 2]);
            }
    }
}

// ---------------------------------------------------------------------------
// Fused QKV projection GEMM. Grid (6144/128 = 48, MROWS/128 = 32).
// W hi/lo stacked [6144 x 2048]. Q,K emit fp32 (B,H,T,Dh) for RoPE;
// V emits truncation-split bf16 hi/lo directly (no RoPE needed).
// ---------------------------------------------------------------------------
__global__ void __launch_bounds__(256) gemm_qkv(
    const __nv_bfloat16* __restrict__ Ah, const __nv_bfloat16* __restrict__ Al,
    const __nv_bfloat16* __restrict__ Wh, const __nv_bfloat16* __restrict__ Wl,
    const float* __restrict__ bq, const float* __restrict__ bk,
    const float* __restrict__ bv,
    float* __restrict__ q, float* __restrict__ k,
    __nv_bfloat16* __restrict__ vh, __nv_bfloat16* __restrict__ vl)
{
    extern __shared__ __align__(128) char smem[];
    const uint32_t sbase = smem_u32(smem);
    const int tid  = threadIdx.x;
    const int wid  = tid >> 5;
    const int lane = tid & 31;
    const int row0  = blockIdx.y * 128;
    const int col0g = blockIdx.x * 128;           // 0..6143 (stacked W rows)
    const int proj  = col0g >> 11;
    const float* bias = (proj == 0) ? bq : (proj == 1) ? bk : bv;
    const int wm = (wid >> 2) * 64;
    const int wn = (wid & 3) * 32;

    float acc[4][4][4];
#pragma unroll
    for (int i = 0; i < 4; i++)
#pragma unroll
        for (int j = 0; j < 4; j++)
#pragma unroll
            for (int c = 0; c < 4; c++) acc[i][j][c] = 0.f;

    const int mi = lane >> 3;
    const int l7 = lane & 7;
    const int a_r  = ((mi & 1) << 3) + l7;
    const int a_kb = (mi >> 1) << 3;
    const int b_nt = mi >> 1;
    const int b_kb = (mi & 1) << 3;

    const int NKT = DM / BK;
    gemm_issue(sbase, 0, 0, tid, row0, col0g, Ah, Al, Wh, Wl);

    for (int kt = 0; kt < NKT; kt++) {
        const int buf = kt & 1;
        if (kt + 1 < NKT) {
            gemm_issue(sbase, buf ^ 1, kt + 1, tid, row0, col0g, Ah, Al, Wh, Wl);
            cpa_wait<1>();
        } else {
            cpa_wait<0>();
        }
        __syncthreads();
        gemm_slab(sbase + buf * BUF_B, wm, wn, a_r, a_kb, b_nt, b_kb, l7, acc);
        __syncthreads();
    }

    // epilogue: scatter to (B,H,T,Dh); V goes straight to split-bf16
#pragma unroll
    for (int mt = 0; mt < 4; mt++) {
#pragma unroll
        for (int nt = 0; nt < 4; nt++) {
            const int nn = (col0g + wn + nt * 8 + (lane & 3) * 2) & (DM - 1);
            const float b0 = bias[nn], b1 = bias[nn + 1];
            const int h  = nn >> 7;
            const int d0 = nn & (DH - 1);
#pragma unroll
            for (int half = 0; half < 2; half++) {
                const int rr = row0 + wm + mt * 16 + (lane >> 2) + half * 8;
                const int b  = rr >> 11;
                const int tt = rr & (SEQ - 1);
                const float o0 = acc[mt][nt][half * 2 + 0] + b0;
                const float o1 = acc[mt][nt][half * 2 + 1] + b1;
                const size_t off = (((size_t)(b * NH + h)) * SEQ + tt) * DH + d0;
                if (proj == 0) {
                    *(float2*)(q + off) = make_float2(o0, o1);
                } else if (proj == 1) {
                    *(float2*)(k + off) = make_float2(o0, o1);
                } else {
                    *(uint32_t*)(vh + off) = pack_hi_trunc(o0, o1);
                    *(uint32_t*)(vl + off) = pack_lo_res(o0, o1);
                }
            }
        }
    }
}

// ---------------------------------------------------------------------------
// Output projection GEMM (plain row-major out). Grid (16, 32).
// ---------------------------------------------------------------------------
__global__ void __launch_bounds__(256) gemm_out(
    const __nv_bfloat16* __restrict__ Ah, const __nv_bfloat16* __restrict__ Al,
    const __nv_bfloat16* __restrict__ Wh, const __nv_bfloat16* __restrict__ Wl,
    const float* __restrict__ bias, float* __restrict__ C)
{
    extern __shared__ __align__(128) char smem[];
    const uint32_t sbase = smem_u32(smem);
    const int tid  = threadIdx.x;
    const int wid  = tid >> 5;
    const int lane = tid & 31;
    const int row0 = blockIdx.y * 128;
    const int col0 = blockIdx.x * 128;
    const int wm = (wid >> 2) * 64;
    const int wn = (wid & 3) * 32;

    float acc[4][4][4];
#pragma unroll
    for (int i = 0; i < 4; i++)
#pragma unroll
        for (int j = 0; j < 4; j++)
#pragma unroll
            for (int c = 0; c < 4; c++) acc[i][j][c] = 0.f;

    const int mi = lane >> 3;
    const int l7 = lane & 7;
    const int a_r  = ((mi & 1) << 3) + l7;
    const int a_kb = (mi >> 1) << 3;
    const int b_nt = mi >> 1;
    const int b_kb = (mi & 1) << 3;

    const int NKT = DM / BK;
    gemm_issue(sbase, 0, 0, tid, row0, col0, Ah, Al, Wh, Wl);

    for (int kt = 0; kt < NKT; kt++) {
        const int buf = kt & 1;
        if (kt + 1 < NKT) {
            gemm_issue(sbase, buf ^ 1, kt + 1, tid, row0, col0, Ah, Al, Wh, Wl);
            cpa_wait<1>();
        } else {
            cpa_wait<0>();
        }
        __syncthreads();
        gemm_slab(sbase + buf * BUF_B, wm, wn, a_r, a_kb, b_nt, b_kb, l7, acc);
        __syncthreads();
    }

#pragma unroll
    for (int mt = 0; mt < 4; mt++) {
#pragma unroll
        for (int nt = 0; nt < 4; nt++) {
            const int cc = col0 + wn + nt * 8 + (lane & 3) * 2;
            const float b0 = bias[cc], b1 = bias[cc + 1];
#pragma unroll
            for (int half = 0; half < 2; half++) {
                const int rr = row0 + wm + mt * 16 + (lane >> 2) + half * 8;
                float2 o;
                o.x = acc[mt][nt][half * 2 + 0] + b0;
                o.y = acc[mt][nt][half * 2 + 1] + b1;
                *(float2*)(C + (size_t)rr * DM + cc) = o;
            }
        }
    }
}

// ---------------------------------------------------------------------------
// RoPE + scale + truncation-split of q,k -> bf16 hi/lo arrays (V done in GEMM)
// ---------------------------------------------------------------------------
__global__ void rope_split(const float* __restrict__ q, const float* __restrict__ k,
                           const float* __restrict__ sn, const float* __restrict__ cs,
                           __nv_bfloat16* __restrict__ qh, __nv_bfloat16* __restrict__ ql,
                           __nv_bfloat16* __restrict__ kh, __nv_bfloat16* __restrict__ kl)
{
    const int idx = blockIdx.x * blockDim.x + threadIdx.x;   // BHN*SEQ*64
    const int d  = idx & 63;
    const int t  = (idx >> 6) & (SEQ - 1);
    const int bh = idx >> 17;
    const float s = sn[t * 64 + d];
    const float c = cs[t * 64 + d];
    const size_t base = ((size_t)bh * SEQ + t) * DH;
    const float scale = 0.08838834764831845f;   // 1/sqrt(128)

    float q1 = q[base + d], q2 = q[base + 64 + d];
    float rq1 = (q1 * c - q2 * s) * scale;
    float rq2 = (q1 * s + q2 * c) * scale;
    __nv_bfloat16 hh, ll;
    tsplit(rq1, &hh, &ll); qh[base + d] = hh;      ql[base + d] = ll;
    tsplit(rq2, &hh, &ll); qh[base + 64 + d] = hh; ql[base + 64 + d] = ll;

    float k1 = k[base + d], k2 = k[base + 64 + d];
    float rk1 = k1 * c - k2 * s;
    float rk2 = k1 * s + k2 * c;
    tsplit(rk1, &hh, &ll); kh[base + d] = hh;      kl[base + d] = ll;
    tsplit(rk2, &hh, &ll); kh[base + 64 + d] = hh; kl[base + 64 + d] = ll;
}

// ---------------------------------------------------------------------------
// Tensor-core causal flash attention, split-bf16, race-free single-sync loop.
// ---------------------------------------------------------------------------
#define FSTR   272
#define QT_B   (128 * FSTR)
#define KT_B   (64 * FSTR)
#define FBUF   (4 * KT_B)
#define FL_SMEM (2 * QT_B + 2 * FBUF)  // 208896

__global__ void __launch_bounds__(256) flash_mma(
    const __nv_bfloat16* __restrict__ qh, const __nv_bfloat16* __restrict__ ql,
    const __nv_bfloat16* __restrict__ kh, const __nv_bfloat16* __restrict__ kl,
    const __nv_bfloat16* __restrict__ vh, const __nv_bfloat16* __restrict__ vl,
    __nv_bfloat16* __restrict__ att_hi, __nv_bfloat16* __restrict__ att_lo)
{
    extern __shared__ __align__(128) char smem[];
    const uint32_t sbase = smem_u32(smem);
    const int tid  = threadIdx.x;
    const int wid  = tid >> 5;
    const int lane = tid & 31;
    const int qt = (int)gridDim.x - 1 - (int)blockIdx.x;  // heavy tiles first
    const int bhid = blockIdx.y;
    const size_t hb = (size_t)bhid * SEQ * DH;

    const int mi_ = lane >> 3;
    const int l7  = lane & 7;
    const int a_r  = ((mi_ & 1) << 3) + l7;
    const int a_kb = (mi_ >> 1) << 3;
    const int b_nt = mi_ >> 1;
    const int b_kb = (mi_ & 1) << 3;

    // ---- load Q tile (hi+lo), its own commit group ----
    {
        const __nv_bfloat16* src[2] = {qh, ql};
#pragma unroll
        for (int i = 0; i < 16; i++) {
            const int idx = tid + i * 256;
            const int t = idx >> 11, r = (idx >> 4) & 127, c = idx & 15;
            cpa16(sbase + t * QT_B + r * FSTR + c * 16,
                  src[t] + hb + (size_t)(qt * 128 + r) * DH + c * 8);
        }
        cpa_commit();
    }

    const __nv_bfloat16* kvsrc[4] = {kh, kl, vh, vl};
    auto issue_kv = [&](int j, int buf) {
        const uint32_t base = sbase + 2 * QT_B + buf * FBUF;
#pragma unroll
        for (int i = 0; i < 16; i++) {
            const int idx = tid + i * 256;
            const int s = idx >> 10, r = (idx >> 4) & 63, c = idx & 15;
            cpa16(base + s * KT_B + r * FSTR + c * 16,
                  kvsrc[s] + hb + (size_t)(j * 64 + r) * DH + c * 8);
        }
        cpa_commit();
    };

    float O[16][4];
#pragma unroll
    for (int nt = 0; nt < 16; nt++)
#pragma unroll
        for (int c = 0; c < 4; c++) O[nt][c] = 0.f;
    float mi0 = -INFINITY, mi1 = -INFINITY, li0 = 0.f, li1 = 0.f;

    const int rbase = qt * 128 + wid * 16;
    const int jmax = 2 * qt + 1;
    issue_kv(0, 0);

    for (int j = 0; j <= jmax; j++) {
        cpa_wait<0>();
        __syncthreads();
        if (j < jmax) issue_kv(j + 1, (j + 1) & 1);
        const int buf = j & 1;

        const bool active = (j * 64 <= rbase + 15);
        if (active) {
            const uint32_t kb = sbase + 2 * QT_B + buf * FBUF;

            // ---- S = Q K^T (split 3-term) ----
            float S[8][4];
#pragma unroll
            for (int nf = 0; nf < 8; nf++)
#pragma unroll
                for (int c = 0; c < 4; c++) S[nf][c] = 0.f;

#pragma unroll
            for (int k16 = 0; k16 < 8; k16++) {
                uint32_t aqh[4], aql[4];
                const uint32_t qa = sbase + (wid * 16 + a_r) * FSTR +
                                    (k16 * 16 + a_kb) * 2;
                ldsm4(aqh, qa);
                ldsm4(aql, qa + QT_B);
                uint32_t kfh[16], kfl[16];
#pragma unroll
                for (int g = 0; g < 4; g++) {
                    const uint32_t ka = kb + ((2 * g + b_nt) * 8 + l7) * FSTR +
                                        (k16 * 16 + b_kb) * 2;
                    ldsm4(&kfh[g * 4], ka);
                    ldsm4(&kfl[g * 4], ka + KT_B);
                }
#pragma unroll
                for (int nf = 0; nf < 8; nf++) {
                    const uint32_t* Bh = &kfh[nf * 2];
                    const uint32_t* Bl = &kfl[nf * 2];
                    mma16816(S[nf], aqh, Bh);
                    mma16816(S[nf], aqh, Bl);
                    mma16816(S[nf], aql, Bh);
                }
            }

            // ---- causal mask ----
            if (j * 64 + 63 > rbase) {
                const int r0 = rbase + (lane >> 2), r1 = r0 + 8;
#pragma unroll
                for (int nf = 0; nf < 8; nf++) {
                    const int c0 = j * 64 + nf * 8 + (lane & 3) * 2;
                    if (c0 > r0)     S[nf][0] = -1e30f;
                    if (c0 + 1 > r0) S[nf][1] = -1e30f;
                    if (c0 > r1)     S[nf][2] = -1e30f;
                    if (c0 + 1 > r1) S[nf][3] = -1e30f;
                }
            }

            // ---- online softmax ----
            float rx0 = -1e30f, rx1 = -1e30f;
#pragma unroll
            for (int nf = 0; nf < 8; nf++) {
                rx0 = fmaxf(rx0, fmaxf(S[nf][0], S[nf][1]));
                rx1 = fmaxf(rx1, fmaxf(S[nf][2], S[nf][3]));
            }
            rx0 = fmaxf(rx0, __shfl_xor_sync(0xffffffffu, rx0, 1));
            rx0 = fmaxf(rx0, __shfl_xor_sync(0xffffffffu, rx0, 2));
            rx1 = fmaxf(rx1, __shfl_xor_sync(0xffffffffu, rx1, 1));
            rx1 = fmaxf(rx1, __shfl_xor_sync(0xffffffffu, rx1, 2));
            const float mn0 = fmaxf(mi0, rx0), mn1 = fmaxf(mi1, rx1);
            const float al0 = __expf(mi0 - mn0), al1 = __expf(mi1 - mn1);
            float s0 = 0.f, s1 = 0.f;
#pragma unroll
            for (int nf = 0; nf < 8; nf++) {
                S[nf][0] = __expf(S[nf][0] - mn0);
                S[nf][1] = __expf(S[nf][1] - mn0);
                S[nf][2] = __expf(S[nf][2] - mn1);
                S[nf][3] = __expf(S[nf][3] - mn1);
                s0 += S[nf][0] + S[nf][1];
                s1 += S[nf][2] + S[nf][3];
            }
            s0 += __shfl_xor_sync(0xffffffffu, s0, 1);
            s0 += __shfl_xor_sync(0xffffffffu, s0, 2);
            s1 += __shfl_xor_sync(0xffffffffu, s1, 1);
            s1 += __shfl_xor_sync(0xffffffffu, s1, 2);
            li0 = li0 * al0 + s0; mi0 = mn0;
            li1 = li1 * al1 + s1; mi1 = mn1;
#pragma unroll
            for (int nt = 0; nt < 16; nt++) {
                O[nt][0] *= al0; O[nt][1] *= al0;
                O[nt][2] *= al1; O[nt][3] *= al1;
            }

            // ---- pack P to A-fragments (truncation split) ----
            uint32_t Ph[4][4], Pl[4][4];
#pragma unroll
            for (int kc = 0; kc < 4; kc++) {
                Ph[kc][0] = pack_hi_trunc(S[2*kc][0],   S[2*kc][1]);
                Ph[kc][1] = pack_hi_trunc(S[2*kc][2],   S[2*kc][3]);
                Ph[kc][2] = pack_hi_trunc(S[2*kc+1][0], S[2*kc+1][1]);
                Ph[kc][3] = pack_hi_trunc(S[2*kc+1][2], S[2*kc+1][3]);
                Pl[kc][0] = pack_lo_res(S[2*kc][0],   S[2*kc][1]);
                Pl[kc][1] = pack_lo_res(S[2*kc][2],   S[2*kc][3]);
                Pl[kc][2] = pack_lo_res(S[2*kc+1][0], S[2*kc+1][1]);
                Pl[kc][3] = pack_lo_res(S[2*kc+1][2], S[2*kc+1][3]);
            }

            // ---- O += P V (split 3-term) ----
            const uint32_t vb = kb + 2 * KT_B;
#pragma unroll
            for (int kc = 0; kc < 4; kc++) {
#pragma unroll
                for (int half = 0; half < 2; half++) {
                    uint32_t vfh[16], vfl[16];
#pragma unroll
                    for (int g = 0; g < 4; g++) {
                        const int gg = half * 4 + g;
                        const uint32_t va = vb +
                            (kc * 16 + ((mi_ & 1) << 3) + l7) * FSTR +
                            (gg * 16 + ((mi_ >> 1) << 3)) * 2;
                        ldsm4t(&vfh[g * 4], va);
                        ldsm4t(&vfl[g * 4], va + KT_B);
                    }
#pragma unroll
                    for (int nf = 0; nf < 8; nf++) {
                        const int nt = half * 8 + nf;
                        const uint32_t* Bh = &vfh[nf * 2];
                        const uint32_t* Bl = &vfl[nf * 2];
                        mma16816(O[nt], Ph[kc], Bh);
                        mma16816(O[nt], Ph[kc], Bl);
                        mma16816(O[nt], Pl[kc], Bh);
                    }
                }
            }
        }
    }

    // ---- epilogue ----
    const float inv0 = 1.f / li0, inv1 = 1.f / li1;
    const int b = bhid >> 4, h = bhid & 15;
    const int t0 = rbase + (lane >> 2), t1 = t0 + 8;
#pragma unroll
    for (int nt = 0; nt < 16; nt++) {
        const int col = h * DH + nt * 8 + (lane & 3) * 2;
        const size_t o0 = ((size_t)(b * SEQ) + t0) * DM + col;
        const size_t o1 = ((size_t)(b * SEQ) + t1) * DM + col;
        const float x0 = O[nt][0] * inv0, x1 = O[nt][1] * inv0;
        const float y0 = O[nt][2] * inv1, y1 = O[nt][3] * inv1;
        *(uint32_t*)(att_hi + o0) = pack_hi_trunc(x0, x1);
        *(uint32_t*)(att_lo + o0) = pack_lo_res(x0, x1);
        *(uint32_t*)(att_hi + o1) = pack_hi_trunc(y0, y1);
        *(uint32_t*)(att_lo + o1) = pack_lo_res(y0, y1);
    }
}

// ---------------------------------------------------------------------------
extern "C" void kernel_launch(void* const* d_in, const int* in_sizes, int n_in,
                              void* d_out, int out_size)
{
    (void)in_sizes; (void)n_in; (void)out_size;
    const float* x  = (const float*)d_in[0];
    const float* Wq = (const float*)d_in[1];
    const float* bq = (const float*)d_in[2];
    const float* Wk = (const float*)d_in[3];
    const float* bk = (const float*)d_in[4];
    const float* Wv = (const float*)d_in[5];
    const float* bv = (const float*)d_in[6];
    const float* Wo = (const float*)d_in[7];
    const float* bo = (const float*)d_in[8];
    const float* sn = (const float*)d_in[9];
    const float* cs = (const float*)d_in[10];
    float* out = (float*)d_out;

    float *q, *k;
    __nv_bfloat16 *xh, *xl, *wh, *wl, *ah, *al;
    __nv_bfloat16 *qh, *ql, *kh, *kl, *vh, *vl;
    cudaGetSymbolAddress((void**)&q,  g_q);
    cudaGetSymbolAddress((void**)&k,  g_k);
    cudaGetSymbolAddress((void**)&xh, g_xh);
    cudaGetSymbolAddress((void**)&xl, g_xl);
    cudaGetSymbolAddress((void**)&wh, g_wh);
    cudaGetSymbolAddress((void**)&wl, g_wl);
    cudaGetSymbolAddress((void**)&ah, g_ah);
    cudaGetSymbolAddress((void**)&al, g_al);
    cudaGetSymbolAddress((void**)&qh, g_qh);
    cudaGetSymbolAddress((void**)&ql, g_ql);
    cudaGetSymbolAddress((void**)&kh, g_kh);
    cudaGetSymbolAddress((void**)&kl, g_kl);
    cudaGetSymbolAddress((void**)&vh, g_vh);
    cudaGetSymbolAddress((void**)&vl, g_vl);

    cudaFuncSetAttribute(gemm_qkv, cudaFuncAttributeMaxDynamicSharedMemorySize, GM_SMEM);
    cudaFuncSetAttribute(gemm_out, cudaFuncAttributeMaxDynamicSharedMemorySize, GM_SMEM);
    cudaFuncSetAttribute(flash_mma, cudaFuncAttributeMaxDynamicSharedMemorySize, FL_SMEM);

    // split conversions: x, then all 4 weight matrices in one launch
    split_kernel<<<(MROWS * DM / 4) / 256, 256>>>(x, xh, xl, MROWS * DM / 4);
    const int wn4 = DM * DM / 4;
    Ptr4 wsrc = {Wq, Wk, Wv, Wo};
    split4_kernel<<<dim3(wn4 / 256, 4), 256>>>(wsrc, wh, wl, wn4);

    // Fused QKV projection (48 x 32 = 1536 CTAs); V split emitted directly
    gemm_qkv<<<dim3(3 * DM / 128, MROWS / 128), 256, GM_SMEM>>>(
        xh, xl, wh, wl, bq, bk, bv, q, k, vh, vl);

    // RoPE + scale + split to bf16 hi/lo (q, k only)
    rope_split<<<(BHN * SEQ * 64) / 256, 256>>>(q, k, sn, cs, qh, ql, kh, kl);

    // Tensor-core flash attention (emits split-bf16 att)
    flash_mma<<<dim3(SEQ / 128, BHN), 256, FL_SMEM>>>(qh, ql, kh, kl, vh, vl, ah, al);

    // Output projection
    gemm_out<<<dim3(DM / 128, MROWS / 128), 256, GM_SMEM>>>(
        ah, al, wh + 3 * (size_t)DM * DM, wl + 3 * (size_t)DM * DM, bo, out);
}

// round 12
// speedup vs baseline: 1.1574x; 1.0114x over previous
#include <cuda_runtime.h>
#include <cuda_bf16.h>
#include <math.h>
#include <stdint.h>

// Problem constants
#define DM   2048
#define NH   16
#define DH   128
#define SEQ  2048
#define BB   2
#define MROWS (BB*SEQ)     // 4096
#define BHN   (BB*NH)      // 32

// ---------------- scratch (static device arrays per harness rules) ----------
__device__ float g_q[BHN * SEQ * DH];
__device__ float g_k[BHN * SEQ * DH];
__device__ __nv_bfloat16 g_xh[MROWS * DM], g_xl[MROWS * DM];
__device__ __nv_bfloat16 g_wh[4 * DM * DM], g_wl[4 * DM * DM];   // q,k,v,o stacked
__device__ __nv_bfloat16 g_ah[MROWS * DM], g_al[MROWS * DM];     // att split
__device__ __nv_bfloat16 g_qh[BHN * SEQ * DH], g_ql[BHN * SEQ * DH];
__device__ __nv_bfloat16 g_kh[BHN * SEQ * DH], g_kl[BHN * SEQ * DH];
__device__ __nv_bfloat16 g_vh[BHN * SEQ * DH], g_vl[BHN * SEQ * DH];

// ---------------- helpers ---------------------------------------------------
__device__ __forceinline__ uint32_t smem_u32(const void* p) {
    uint32_t a;
    asm("{ .reg .u64 t; cvta.to.shared.u64 t, %1; cvt.u32.u64 %0, t; }"
        : "=r"(a) : "l"(p));
    return a;
}
__device__ __forceinline__ void cpa16(uint32_t s, const void* g) {
    asm volatile("cp.async.cg.shared.global [%0], [%1], 16;" :: "r"(s), "l"(g));
}
__device__ __forceinline__ void cpa_commit() {
    asm volatile("cp.async.commit_group;" ::: "memory");
}
template<int N>
__device__ __forceinline__ void cpa_wait() {
    asm volatile("cp.async.wait_group %0;" :: "n"(N) : "memory");
}
__device__ __forceinline__ void ldsm4(uint32_t* r, uint32_t addr) {
    asm volatile("ldmatrix.sync.aligned.m8n8.x4.shared.b16 {%0,%1,%2,%3}, [%4];"
                 : "=r"(r[0]), "=r"(r[1]), "=r"(r[2]), "=r"(r[3]) : "r"(addr));
}
__device__ __forceinline__ void ldsm4t(uint32_t* r, uint32_t addr) {
    asm volatile("ldmatrix.sync.aligned.m8n8.x4.trans.shared.b16 {%0,%1,%2,%3}, [%4];"
                 : "=r"(r[0]), "=r"(r[1]), "=r"(r[2]), "=r"(r[3]) : "r"(addr));
}
__device__ __forceinline__ void mma16816(float* c, const uint32_t* a, const uint32_t* b) {
    asm volatile("mma.sync.aligned.m16n8k16.row.col.f32.bf16.bf16.f32 "
                 "{%0,%1,%2,%3}, {%4,%5,%6,%7}, {%8,%9}, {%0,%1,%2,%3};"
                 : "+f"(c[0]), "+f"(c[1]), "+f"(c[2]), "+f"(c[3])
                 : "r"(a[0]), "r"(a[1]), "r"(a[2]), "r"(a[3]),
                   "r"(b[0]), "r"(b[1]));
}
__device__ __forceinline__ uint32_t pack_hi_trunc(float a, float b) {
    return __byte_perm(__float_as_uint(a), __float_as_uint(b), 0x7632);
}
__device__ __forceinline__ uint32_t pack_lo_res(float a, float b) {
    float ra = a - __uint_as_float(__float_as_uint(a) & 0xFFFF0000u);
    float rb = b - __uint_as_float(__float_as_uint(b) & 0xFFFF0000u);
    uint32_t r;
    asm("cvt.rn.bf16x2.f32 %0, %1, %2;" : "=r"(r) : "f"(rb), "f"(ra));
    return r;
}
__device__ __forceinline__ float fex2(float x) {
    float y;
    asm("ex2.approx.ftz.f32 %0, %1;" : "=f"(y) : "f"(x));
    return y;
}

// ---------------------------------------------------------------------------
// fp32 -> (hi, lo) bf16 split, vectorized x4 (single tensor)
// ---------------------------------------------------------------------------
__global__ void split_kernel(const float* __restrict__ src,
                             __nv_bfloat16* __restrict__ hi,
                             __nv_bfloat16* __restrict__ lo, int n4)
{
    int i = blockIdx.x * blockDim.x + threadIdx.x;
    if (i >= n4) return;
    float4 v = ((const float4*)src)[i];
    __nv_bfloat16 h0 = __float2bfloat16(v.x), h1 = __float2bfloat16(v.y);
    __nv_bfloat16 h2 = __float2bfloat16(v.z), h3 = __float2bfloat16(v.w);
    __nv_bfloat16 l0 = __float2bfloat16(v.x - __bfloat162float(h0));
    __nv_bfloat16 l1 = __float2bfloat16(v.y - __bfloat162float(h1));
    __nv_bfloat16 l2 = __float2bfloat16(v.z - __bfloat162float(h2));
    __nv_bfloat16 l3 = __float2bfloat16(v.w - __bfloat162float(h3));
    ((__nv_bfloat162*)hi)[2 * i]     = __halves2bfloat162(h0, h1);
    ((__nv_bfloat162*)hi)[2 * i + 1] = __halves2bfloat162(h2, h3);
    ((__nv_bfloat162*)lo)[2 * i]     = __halves2bfloat162(l0, l1);
    ((__nv_bfloat162*)lo)[2 * i + 1] = __halves2bfloat162(l2, l3);
}

// 4 weight matrices in one launch (blockIdx.y selects source)
struct Ptr4 { const float* p0; const float* p1; const float* p2; const float* p3; };
__global__ void split4_kernel(Ptr4 srcs,
                              __nv_bfloat16* __restrict__ hi,
                              __nv_bfloat16* __restrict__ lo, int n4per)
{
    int i = blockIdx.x * blockDim.x + threadIdx.x;
    if (i >= n4per) return;
    const float* src = (blockIdx.y == 0) ? srcs.p0 : (blockIdx.y == 1) ? srcs.p1
                     : (blockIdx.y == 2) ? srcs.p2 : srcs.p3;
    const size_t o = (size_t)blockIdx.y * n4per + i;
    float4 v = ((const float4*)src)[i];
    __nv_bfloat16 h0 = __float2bfloat16(v.x), h1 = __float2bfloat16(v.y);
    __nv_bfloat16 h2 = __float2bfloat16(v.z), h3 = __float2bfloat16(v.w);
    __nv_bfloat16 l0 = __float2bfloat16(v.x - __bfloat162float(h0));
    __nv_bfloat16 l1 = __float2bfloat16(v.y - __bfloat162float(h1));
    __nv_bfloat16 l2 = __float2bfloat16(v.z - __bfloat162float(h2));
    __nv_bfloat16 l3 = __float2bfloat16(v.w - __bfloat162float(h3));
    ((__nv_bfloat162*)hi)[2 * o]     = __halves2bfloat162(h0, h1);
    ((__nv_bfloat162*)hi)[2 * o + 1] = __halves2bfloat162(h2, h3);
    ((__nv_bfloat162*)lo)[2 * o]     = __halves2bfloat162(l0, l1);
    ((__nv_bfloat162*)lo)[2 * o + 1] = __halves2bfloat162(l2, l3);
}

// ---------------------------------------------------------------------------
// Shared GEMM machinery: 128x128 CTA tile, BK=32, 2-stage cp.async pipeline,
// ONE barrier per slab (wait -> sync -> issue next -> compute; the single
// barrier orders kt-1's reads of buf^1 before kt's overwrite of buf^1).
// 2 stages = 81920 B smem = 2 CTAs/SM (occupancy measured decisive in R8/R9).
// ---------------------------------------------------------------------------
#define BK    32
#define TSTR  40
#define TILE_B (128 * TSTR * 2)     // 10240 B
#define BUF_B  (4 * TILE_B)         // 40960 B / stage
#define GM_SMEM (2 * BUF_B)         // 81920 B

// Per-stage tile load (Ah, Al, Wh, Wl), 128 rows x 32 bf16 each
__device__ __forceinline__ void gemm_issue(
    uint32_t sbase, int buf, int kt, int tid, int row0, int wrow0,
    const __nv_bfloat16* Ah, const __nv_bfloat16* Al,
    const __nv_bfloat16* Wh, const __nv_bfloat16* Wl)
{
    const __nv_bfloat16* gsrc[4] = {Ah, Al, Wh, Wl};
#pragma unroll
    for (int t = 0; t < 4; t++) {
        const __nv_bfloat16* g = gsrc[t];
        const int rb = (t < 2) ? row0 : wrow0;
        const uint32_t sb = sbase + buf * BUF_B + t * TILE_B;
#pragma unroll
        for (int i = 0; i < 2; i++) {
            const int ch = tid + i * 256;
            const int r = ch >> 2, c = ch & 3;
            cpa16(sb + r * (TSTR * 2) + c * 16,
                  g + (size_t)(rb + r) * DM + kt * BK + c * 8);
        }
    }
    cpa_commit();
}

// Mainloop body: accumulate one K-slab from stage buffer sb
__device__ __forceinline__ void gemm_slab(
    uint32_t sb, int wm, int wn, int a_r, int a_kb, int b_nt, int b_kb, int l7,
    float acc[4][4][4])
{
#pragma unroll
    for (int kh = 0; kh < 2; kh++) {
        uint32_t afh[4][4], afl[4][4];
#pragma unroll
        for (int mt = 0; mt < 4; mt++) {
            const uint32_t ad = sb +
                (wm + mt * 16 + a_r) * (TSTR * 2) + (kh * 16 + a_kb) * 2;
            ldsm4(afh[mt], ad);
            ldsm4(afl[mt], ad + TILE_B);
        }
        uint32_t bfh[8], bfl[8];
#pragma unroll
        for (int g = 0; g < 2; g++) {
            const uint32_t bd = sb + 2 * TILE_B +
                (wn + (2 * g + b_nt) * 8 + l7) * (TSTR * 2) +
                (kh * 16 + b_kb) * 2;
            ldsm4(&bfh[g * 4], bd);
            ldsm4(&bfl[g * 4], bd + TILE_B);
        }
#pragma unroll
        for (int mt = 0; mt < 4; mt++)
#pragma unroll
            for (int nt = 0; nt < 4; nt++) {
                float* c = acc[mt][nt];
                mma16816(c, afh[mt], &bfh[nt * 2]);
                mma16816(c, afh[mt], &bfl[nt * 2]);
                mma16816(c, afl[mt], &bfh[nt * 2]);
            }
    }
}

// ---------------------------------------------------------------------------
// Fused QKV projection GEMM. Grid (6144/128 = 48, MROWS/128 = 32).
// W hi/lo stacked [6144 x 2048]. Q,K emit fp32 (B,H,T,Dh) for RoPE;
// V emits truncation-split bf16 hi/lo directly (no RoPE needed).
// ---------------------------------------------------------------------------
__global__ void __launch_bounds__(256) gemm_qkv(
    const __nv_bfloat16* __restrict__ Ah, const __nv_bfloat16* __restrict__ Al,
    const __nv_bfloat16* __restrict__ Wh, const __nv_bfloat16* __restrict__ Wl,
    const float* __restrict__ bq, const float* __restrict__ bk,
    const float* __restrict__ bv,
    float* __restrict__ q, float* __restrict__ k,
    __nv_bfloat16* __restrict__ vh, __nv_bfloat16* __restrict__ vl)
{
    extern __shared__ __align__(128) char smem[];
    const uint32_t sbase = smem_u32(smem);
    const int tid  = threadIdx.x;
    const int wid  = tid >> 5;
    const int lane = tid & 31;
    const int row0  = blockIdx.y * 128;
    const int col0g = blockIdx.x * 128;           // 0..6143 (stacked W rows)
    const int proj  = col0g >> 11;
    const float* bias = (proj == 0) ? bq : (proj == 1) ? bk : bv;
    const int wm = (wid >> 2) * 64;
    const int wn = (wid & 3) * 32;

    float acc[4][4][4];
#pragma unroll
    for (int i = 0; i < 4; i++)
#pragma unroll
        for (int j = 0; j < 4; j++)
#pragma unroll
            for (int c = 0; c < 4; c++) acc[i][j][c] = 0.f;

    const int mi = lane >> 3;
    const int l7 = lane & 7;
    const int a_r  = ((mi & 1) << 3) + l7;
    const int a_kb = (mi >> 1) << 3;
    const int b_nt = mi >> 1;
    const int b_kb = (mi & 1) << 3;

    const int NKT = DM / BK;
    gemm_issue(sbase, 0, 0, tid, row0, col0g, Ah, Al, Wh, Wl);

    for (int kt = 0; kt < NKT; kt++) {
        const int buf = kt & 1;
        cpa_wait<0>();
        __syncthreads();
        if (kt + 1 < NKT)
            gemm_issue(sbase, buf ^ 1, kt + 1, tid, row0, col0g, Ah, Al, Wh, Wl);
        gemm_slab(sbase + buf * BUF_B, wm, wn, a_r, a_kb, b_nt, b_kb, l7, acc);
    }

    // epilogue: scatter to (B,H,T,Dh); V goes straight to split-bf16
#pragma unroll
    for (int mt = 0; mt < 4; mt++) {
#pragma unroll
        for (int nt = 0; nt < 4; nt++) {
            const int nn = (col0g + wn + nt * 8 + (lane & 3) * 2) & (DM - 1);
            const float b0 = bias[nn], b1 = bias[nn + 1];
            const int h  = nn >> 7;
            const int d0 = nn & (DH - 1);
#pragma unroll
            for (int half = 0; half < 2; half++) {
                const int rr = row0 + wm + mt * 16 + (lane >> 2) + half * 8;
                const int b  = rr >> 11;
                const int tt = rr & (SEQ - 1);
                const float o0 = acc[mt][nt][half * 2 + 0] + b0;
                const float o1 = acc[mt][nt][half * 2 + 1] + b1;
                const size_t off = (((size_t)(b * NH + h)) * SEQ + tt) * DH + d0;
                if (proj == 0) {
                    *(float2*)(q + off) = make_float2(o0, o1);
                } else if (proj == 1) {
                    *(float2*)(k + off) = make_float2(o0, o1);
                } else {
                    *(uint32_t*)(vh + off) = pack_hi_trunc(o0, o1);
                    *(uint32_t*)(vl + off) = pack_lo_res(o0, o1);
                }
            }
        }
    }
}

// ---------------------------------------------------------------------------
// Output projection GEMM (plain row-major out). Grid (16, 32).
// ---------------------------------------------------------------------------
__global__ void __launch_bounds__(256) gemm_out(
    const __nv_bfloat16* __restrict__ Ah, const __nv_bfloat16* __restrict__ Al,
    const __nv_bfloat16* __restrict__ Wh, const __nv_bfloat16* __restrict__ Wl,
    const float* __restrict__ bias, float* __restrict__ C)
{
    extern __shared__ __align__(128) char smem[];
    const uint32_t sbase = smem_u32(smem);
    const int tid  = threadIdx.x;
    const int wid  = tid >> 5;
    const int lane = tid & 31;
    const int row0 = blockIdx.y * 128;
    const int col0 = blockIdx.x * 128;
    const int wm = (wid >> 2) * 64;
    const int wn = (wid & 3) * 32;

    float acc[4][4][4];
#pragma unroll
    for (int i = 0; i < 4; i++)
#pragma unroll
        for (int j = 0; j < 4; j++)
#pragma unroll
            for (int c = 0; c < 4; c++) acc[i][j][c] = 0.f;

    const int mi = lane >> 3;
    const int l7 = lane & 7;
    const int a_r  = ((mi & 1) << 3) + l7;
    const int a_kb = (mi >> 1) << 3;
    const int b_nt = mi >> 1;
    const int b_kb = (mi & 1) << 3;

    const int NKT = DM / BK;
    gemm_issue(sbase, 0, 0, tid, row0, col0, Ah, Al, Wh, Wl);

    for (int kt = 0; kt < NKT; kt++) {
        const int buf = kt & 1;
        cpa_wait<0>();
        __syncthreads();
        if (kt + 1 < NKT)
            gemm_issue(sbase, buf ^ 1, kt + 1, tid, row0, col0, Ah, Al, Wh, Wl);
        gemm_slab(sbase + buf * BUF_B, wm, wn, a_r, a_kb, b_nt, b_kb, l7, acc);
    }

#pragma unroll
    for (int mt = 0; mt < 4; mt++) {
#pragma unroll
        for (int nt = 0; nt < 4; nt++) {
            const int cc = col0 + wn + nt * 8 + (lane & 3) * 2;
            const float b0 = bias[cc], b1 = bias[cc + 1];
#pragma unroll
            for (int half = 0; half < 2; half++) {
                const int rr = row0 + wm + mt * 16 + (lane >> 2) + half * 8;
                float2 o;
                o.x = acc[mt][nt][half * 2 + 0] + b0;
                o.y = acc[mt][nt][half * 2 + 1] + b1;
                *(float2*)(C + (size_t)rr * DM + cc) = o;
            }
        }
    }
}

// ---------------------------------------------------------------------------
// RoPE + scale + truncation-split of q,k -> bf16 hi/lo arrays, float2 wide.
// Q is pre-scaled by (1/sqrt(128)) * log2(e): flash softmax runs in base 2.
// ---------------------------------------------------------------------------
__global__ void rope_split(const float* __restrict__ q, const float* __restrict__ k,
                           const float* __restrict__ sn, const float* __restrict__ cs,
                           __nv_bfloat16* __restrict__ qh, __nv_bfloat16* __restrict__ ql,
                           __nv_bfloat16* __restrict__ kh, __nv_bfloat16* __restrict__ kl)
{
    const int idx = blockIdx.x * blockDim.x + threadIdx.x;   // BHN*SEQ*32
    const int d2 = (idx & 31) * 2;
    const int t  = (idx >> 5) & (SEQ - 1);
    const int bh = idx >> 16;
    const float2 s2 = *(const float2*)(sn + t * 64 + d2);
    const float2 c2 = *(const float2*)(cs + t * 64 + d2);
    const size_t base = ((size_t)bh * SEQ + t) * DH;
    const float scl = 0.08838834764831845f * 1.4426950408889634f;  // 1/sqrt(128)*log2e

    float2 qa = *(const float2*)(q + base + d2);
    float2 qb = *(const float2*)(q + base + 64 + d2);
    float r0 = (qa.x * c2.x - qb.x * s2.x) * scl;
    float r1 = (qa.y * c2.y - qb.y * s2.y) * scl;
    float r2 = (qa.x * s2.x + qb.x * c2.x) * scl;
    float r3 = (qa.y * s2.y + qb.y * c2.y) * scl;
    *(uint32_t*)(qh + base + d2)      = pack_hi_trunc(r0, r1);
    *(uint32_t*)(ql + base + d2)      = pack_lo_res(r0, r1);
    *(uint32_t*)(qh + base + 64 + d2) = pack_hi_trunc(r2, r3);
    *(uint32_t*)(ql + base + 64 + d2) = pack_lo_res(r2, r3);

    float2 ka = *(const float2*)(k + base + d2);
    float2 kb = *(const float2*)(k + base + 64 + d2);
    float u0 = ka.x * c2.x - kb.x * s2.x;
    float u1 = ka.y * c2.y - kb.y * s2.y;
    float u2 = ka.x * s2.x + kb.x * c2.x;
    float u3 = ka.y * s2.y + kb.y * c2.y;
    *(uint32_t*)(kh + base + d2)      = pack_hi_trunc(u0, u1);
    *(uint32_t*)(kl + base + d2)      = pack_lo_res(u0, u1);
    *(uint32_t*)(kh + base + 64 + d2) = pack_hi_trunc(u2, u3);
    *(uint32_t*)(kl + base + 64 + d2) = pack_lo_res(u2, u3);
}

// ---------------------------------------------------------------------------
// Tensor-core causal flash attention, split-bf16, base-2 softmax (ex2).
// ---------------------------------------------------------------------------
#define FSTR   272
#define QT_B   (128 * FSTR)
#define KT_B   (64 * FSTR)
#define FBUF   (4 * KT_B)
#define FL_SMEM (2 * QT_B + 2 * FBUF)  // 208896

__global__ void __launch_bounds__(256) flash_mma(
    const __nv_bfloat16* __restrict__ qh, const __nv_bfloat16* __restrict__ ql,
    const __nv_bfloat16* __restrict__ kh, const __nv_bfloat16* __restrict__ kl,
    const __nv_bfloat16* __restrict__ vh, const __nv_bfloat16* __restrict__ vl,
    __nv_bfloat16* __restrict__ att_hi, __nv_bfloat16* __restrict__ att_lo)
{
    extern __shared__ __align__(128) char smem[];
    const uint32_t sbase = smem_u32(smem);
    const int tid  = threadIdx.x;
    const int wid  = tid >> 5;
    const int lane = tid & 31;
    const int qt = (int)gridDim.x - 1 - (int)blockIdx.x;  // heavy tiles first
    const int bhid = blockIdx.y;
    const size_t hb = (size_t)bhid * SEQ * DH;

    const int mi_ = lane >> 3;
    const int l7  = lane & 7;
    const int a_r  = ((mi_ & 1) << 3) + l7;
    const int a_kb = (mi_ >> 1) << 3;
    const int b_nt = mi_ >> 1;
    const int b_kb = (mi_ & 1) << 3;

    // ---- load Q tile (hi+lo), its own commit group ----
    {
        const __nv_bfloat16* src[2] = {qh, ql};
#pragma unroll
        for (int i = 0; i < 16; i++) {
            const int idx = tid + i * 256;
            const int t = idx >> 11, r = (idx >> 4) & 127, c = idx & 15;
            cpa16(sbase + t * QT_B + r * FSTR + c * 16,
                  src[t] + hb + (size_t)(qt * 128 + r) * DH + c * 8);
        }
        cpa_commit();
    }

    const __nv_bfloat16* kvsrc[4] = {kh, kl, vh, vl};
    auto issue_kv = [&](int j, int buf) {
        const uint32_t base = sbase + 2 * QT_B + buf * FBUF;
#pragma unroll
        for (int i = 0; i < 16; i++) {
            const int idx = tid + i * 256;
            const int s = idx >> 10, r = (idx >> 4) & 63, c = idx & 15;
            cpa16(base + s * KT_B + r * FSTR + c * 16,
                  kvsrc[s] + hb + (size_t)(j * 64 + r) * DH + c * 8);
        }
        cpa_commit();
    };

    float O[16][4];
#pragma unroll
    for (int nt = 0; nt < 16; nt++)
#pragma unroll
        for (int c = 0; c < 4; c++) O[nt][c] = 0.f;
    float mi0 = -INFINITY, mi1 = -INFINITY, li0 = 0.f, li1 = 0.f;

    const int rbase = qt * 128 + wid * 16;
    const int jmax = 2 * qt + 1;
    issue_kv(0, 0);

    for (int j = 0; j <= jmax; j++) {
        cpa_wait<0>();
        __syncthreads();
        if (j < jmax) issue_kv(j + 1, (j + 1) & 1);
        const int buf = j & 1;

        const bool active = (j * 64 <= rbase + 15);
        if (active) {
            const uint32_t kb = sbase + 2 * QT_B + buf * FBUF;

            // ---- S = Q K^T (split 3-term), log2-domain scores ----
            float S[8][4];
#pragma unroll
            for (int nf = 0; nf < 8; nf++)
#pragma unroll
                for (int c = 0; c < 4; c++) S[nf][c] = 0.f;

#pragma unroll
            for (int k16 = 0; k16 < 8; k16++) {
                uint32_t aqh[4], aql[4];
                const uint32_t qa = sbase + (wid * 16 + a_r) * FSTR +
                                    (k16 * 16 + a_kb) * 2;
                ldsm4(aqh, qa);
                ldsm4(aql, qa + QT_B);
                uint32_t kfh[16], kfl[16];
#pragma unroll
                for (int g = 0; g < 4; g++) {
                    const uint32_t ka = kb + ((2 * g + b_nt) * 8 + l7) * FSTR +
                                        (k16 * 16 + b_kb) * 2;
                    ldsm4(&kfh[g * 4], ka);
                    ldsm4(&kfl[g * 4], ka + KT_B);
                }
#pragma unroll
                for (int nf = 0; nf < 8; nf++) {
                    const uint32_t* Bh = &kfh[nf * 2];
                    const uint32_t* Bl = &kfl[nf * 2];
                    mma16816(S[nf], aqh, Bh);
                    mma16816(S[nf], aqh, Bl);
                    mma16816(S[nf], aql, Bh);
                }
            }

            // ---- causal mask ----
            if (j * 64 + 63 > rbase) {
                const int r0 = rbase + (lane >> 2), r1 = r0 + 8;
#pragma unroll
                for (int nf = 0; nf < 8; nf++) {
                    const int c0 = j * 64 + nf * 8 + (lane & 3) * 2;
                    if (c0 > r0)     S[nf][0] = -1e30f;
                    if (c0 + 1 > r0) S[nf][1] = -1e30f;
                    if (c0 > r1)     S[nf][2] = -1e30f;
                    if (c0 + 1 > r1) S[nf][3] = -1e30f;
                }
            }

            // ---- online softmax (base 2) ----
            float rx0 = -1e30f, rx1 = -1e30f;
#pragma unroll
            for (int nf = 0; nf < 8; nf++) {
                rx0 = fmaxf(rx0, fmaxf(S[nf][0], S[nf][1]));
                rx1 = fmaxf(rx1, fmaxf(S[nf][2], S[nf][3]));
            }
            rx0 = fmaxf(rx0, __shfl_xor_sync(0xffffffffu, rx0, 1));
            rx0 = fmaxf(rx0, __shfl_xor_sync(0xffffffffu, rx0, 2));
            rx1 = fmaxf(rx1, __shfl_xor_sync(0xffffffffu, rx1, 1));
            rx1 = fmaxf(rx1, __shfl_xor_sync(0xffffffffu, rx1, 2));
            const float mn0 = fmaxf(mi0, rx0), mn1 = fmaxf(mi1, rx1);
            const float al0 = fex2(mi0 - mn0), al1 = fex2(mi1 - mn1);
            float s0 = 0.f, s1 = 0.f;
#pragma unroll
            for (int nf = 0; nf < 8; nf++) {
                S[nf][0] = fex2(S[nf][0] - mn0);
                S[nf][1] = fex2(S[nf][1] - mn0);
                S[nf][2] = fex2(S[nf][2] - mn1);
                S[nf][3] = fex2(S[nf][3] - mn1);
                s0 += S[nf][0] + S[nf][1];
                s1 += S[nf][2] + S[nf][3];
            }
            s0 += __shfl_xor_sync(0xffffffffu, s0, 1);
            s0 += __shfl_xor_sync(0xffffffffu, s0, 2);
            s1 += __shfl_xor_sync(0xffffffffu, s1, 1);
            s1 += __shfl_xor_sync(0xffffffffu, s1, 2);
            li0 = li0 * al0 + s0; mi0 = mn0;
            li1 = li1 * al1 + s1; mi1 = mn1;
#pragma unroll
            for (int nt = 0; nt < 16; nt++) {
                O[nt][0] *= al0; O[nt][1] *= al0;
                O[nt][2] *= al1; O[nt][3] *= al1;
            }

            // ---- pack P to A-fragments (truncation split) ----
            uint32_t Ph[4][4], Pl[4][4];
#pragma unroll
            for (int kc = 0; kc < 4; kc++) {
                Ph[kc][0] = pack_hi_trunc(S[2*kc][0],   S[2*kc][1]);
                Ph[kc][1] = pack_hi_trunc(S[2*kc][2],   S[2*kc][3]);
                Ph[kc][2] = pack_hi_trunc(S[2*kc+1][0], S[2*kc+1][1]);
                Ph[kc][3] = pack_hi_trunc(S[2*kc+1][2], S[2*kc+1][3]);
                Pl[kc][0] = pack_lo_res(S[2*kc][0],   S[2*kc][1]);
                Pl[kc][1] = pack_lo_res(S[2*kc][2],   S[2*kc][3]);
                Pl[kc][2] = pack_lo_res(S[2*kc+1][0], S[2*kc+1][1]);
                Pl[kc][3] = pack_lo_res(S[2*kc+1][2], S[2*kc+1][3]);
            }

            // ---- O += P V (split 3-term) ----
            const uint32_t vb = kb + 2 * KT_B;
#pragma unroll
            for (int kc = 0; kc < 4; kc++) {
#pragma unroll
                for (int half = 0; half < 2; half++) {
                    uint32_t vfh[16], vfl[16];
#pragma unroll
                    for (int g = 0; g < 4; g++) {
                        const int gg = half * 4 + g;
                        const uint32_t va = vb +
                            (kc * 16 + ((mi_ & 1) << 3) + l7) * FSTR +
                            (gg * 16 + ((mi_ >> 1) << 3)) * 2;
                        ldsm4t(&vfh[g * 4], va);
                        ldsm4t(&vfl[g * 4], va + KT_B);
                    }
#pragma unroll
                    for (int nf = 0; nf < 8; nf++) {
                        const int nt = half * 8 + nf;
                        const uint32_t* Bh = &vfh[nf * 2];
                        const uint32_t* Bl = &vfl[nf * 2];
                        mma16816(O[nt], Ph[kc], Bh);
                        mma16816(O[nt], Ph[kc], Bl);
                        mma16816(O[nt], Pl[kc], Bh);
                    }
                }
            }
        }
    }

    // ---- epilogue ----
    const float inv0 = 1.f / li0, inv1 = 1.f / li1;
    const int b = bhid >> 4, h = bhid & 15;
    const int t0 = rbase + (lane >> 2), t1 = t0 + 8;
#pragma unroll
    for (int nt = 0; nt < 16; nt++) {
        const int col = h * DH + nt * 8 + (lane & 3) * 2;
        const size_t o0 = ((size_t)(b * SEQ) + t0) * DM + col;
        const size_t o1 = ((size_t)(b * SEQ) + t1) * DM + col;
        const float x0 = O[nt][0] * inv0, x1 = O[nt][1] * inv0;
        const float y0 = O[nt][2] * inv1, y1 = O[nt][3] * inv1;
        *(uint32_t*)(att_hi + o0) = pack_hi_trunc(x0, x1);
        *(uint32_t*)(att_lo + o0) = pack_lo_res(x0, x1);
        *(uint32_t*)(att_hi + o1) = pack_hi_trunc(y0, y1);
        *(uint32_t*)(att_lo + o1) = pack_lo_res(y0, y1);
    }
}

// ---------------------------------------------------------------------------
extern "C" void kernel_launch(void* const* d_in, const int* in_sizes, int n_in,
                              void* d_out, int out_size)
{
    (void)in_sizes; (void)n_in; (void)out_size;
    const float* x  = (const float*)d_in[0];
    const float* Wq = (const float*)d_in[1];
    const float* bq = (const float*)d_in[2];
    const float* Wk = (const float*)d_in[3];
    const float* bk = (const float*)d_in[4];
    const float* Wv = (const float*)d_in[5];
    const float* bv = (const float*)d_in[6];
    const float* Wo = (const float*)d_in[7];
    const float* bo = (const float*)d_in[8];
    const float* sn = (const float*)d_in[9];
    const float* cs = (const float*)d_in[10];
    float* out = (float*)d_out;

    float *q, *k;
    __nv_bfloat16 *xh, *xl, *wh, *wl, *ah, *al;
    __nv_bfloat16 *qh, *ql, *kh, *kl, *vh, *vl;
    cudaGetSymbolAddress((void**)&q,  g_q);
    cudaGetSymbolAddress((void**)&k,  g_k);
    cudaGetSymbolAddress((void**)&xh, g_xh);
    cudaGetSymbolAddress((void**)&xl, g_xl);
    cudaGetSymbolAddress((void**)&wh, g_wh);
    cudaGetSymbolAddress((void**)&wl, g_wl);
    cudaGetSymbolAddress((void**)&ah, g_ah);
    cudaGetSymbolAddress((void**)&al, g_al);
    cudaGetSymbolAddress((void**)&qh, g_qh);
    cudaGetSymbolAddress((void**)&ql, g_ql);
    cudaGetSymbolAddress((void**)&kh, g_kh);
    cudaGetSymbolAddress((void**)&kl, g_kl);
    cudaGetSymbolAddress((void**)&vh, g_vh);
    cudaGetSymbolAddress((void**)&vl, g_vl);

    cudaFuncSetAttribute(gemm_qkv, cudaFuncAttributeMaxDynamicSharedMemorySize, GM_SMEM);
    cudaFuncSetAttribute(gemm_out, cudaFuncAttributeMaxDynamicSharedMemorySize, GM_SMEM);
    cudaFuncSetAttribute(flash_mma, cudaFuncAttributeMaxDynamicSharedMemorySize, FL_SMEM);

    // split conversions: x, then all 4 weight matrices in one launch
    split_kernel<<<(MROWS * DM / 4) / 256, 256>>>(x, xh, xl, MROWS * DM / 4);
    const int wn4 = DM * DM / 4;
    Ptr4 wsrc = {Wq, Wk, Wv, Wo};
    split4_kernel<<<dim3(wn4 / 256, 4), 256>>>(wsrc, wh, wl, wn4);

    // Fused QKV projection (48 x 32 = 1536 CTAs); V split emitted directly
    gemm_qkv<<<dim3(3 * DM / 128, MROWS / 128), 256, GM_SMEM>>>(
        xh, xl, wh, wl, bq, bk, bv, q, k, vh, vl);

    // RoPE + scale(log2e) + split to bf16 hi/lo (q, k only)
    rope_split<<<(BHN * SEQ * 32) / 256, 256>>>(q, k, sn, cs, qh, ql, kh, kl);

    // Tensor-core flash attention (emits split-bf16 att)
    flash_mma<<<dim3(SEQ / 128, BHN), 256, FL_SMEM>>>(qh, ql, kh, kl, vh, vl, ah, al);

    // Output projection
    gemm_out<<<dim3(DM / 128, MROWS / 128), 256, GM_SMEM>>>(
        ah, al, wh + 3 * (size_t)DM * DM, wl + 3 * (size_t)DM * DM, bo, out);
}